// round 14
// baseline (speedup 1.0000x reference)
#include <cuda_runtime.h>
#include <cuda_fp16.h>
#include <cstdint>

#define BSZ   8192
#define DDIM  1024
#define NODES 4096
#define GRIDW 64
#define D2_MAX 4956          // integer d2 <= 4956 <=> sqrt(d2) <= radius (exact)
#define MARGIN 0.6f
#define CAP 16

// ---------------- scratch ----------------
__device__ unsigned long long g_bmu[BSZ];
__device__ unsigned g_tmin[BSZ * 16];          // per-row per-tile min (ordered u32)
__device__ int g_ccnt[BSZ * 16];               // per-row per-tile candidate count
__device__ unsigned g_cand[(size_t)BSZ * 16 * CAP];  // (node<<16)|fp16 score
__device__ float g_Y[NODES * DDIM];
__device__ float g_T[NODES * DDIM];
__device__ float g_cnt[NODES];
__device__ float g_m2[NODES];
__device__ float g_cs[NODES];
__device__ float g_T2[NODES];                  // pj-conv of histogram: T2[pi*64+nj]
__device__ __half g_xh[BSZ * DDIM];
__device__ __half g_mh[NODES * DDIM];

__device__ __forceinline__ float neg_inv_2r2() {
    const float r = 70.4f + 1e-6f;
    return -1.0f / (2.0f * r * r);
}
static __device__ __forceinline__ uint32_t smem_u32(const void* p) {
    uint32_t a;
    asm("{ .reg .u64 t; cvta.to.shared.u64 t, %1; cvt.u32.u64 %0, t; }" : "=r"(a) : "l"(p));
    return a;
}
static __device__ __forceinline__ void mma_f16(float* c, const uint32_t* a, const uint32_t* b) {
    asm volatile(
        "mma.sync.aligned.m16n8k16.row.col.f32.f16.f16.f32 "
        "{%0,%1,%2,%3}, {%4,%5,%6,%7}, {%8,%9}, {%0,%1,%2,%3};"
        : "+f"(c[0]), "+f"(c[1]), "+f"(c[2]), "+f"(c[3])
        : "r"(a[0]), "r"(a[1]), "r"(a[2]), "r"(a[3]), "r"(b[0]), "r"(b[1]));
}
static __device__ __forceinline__ void ldsm_x4(uint32_t* r, uint32_t addr) {
    asm volatile("ldmatrix.sync.aligned.m8n8.x4.shared.b16 {%0,%1,%2,%3}, [%4];"
                 : "=r"(r[0]), "=r"(r[1]), "=r"(r[2]), "=r"(r[3]) : "r"(addr));
}
static __device__ __forceinline__ void cp16(uint32_t dst, const void* src) {
    asm volatile("cp.async.cg.shared.global [%0], [%1], 16;" :: "r"(dst), "l"(src));
}
#define CP_COMMIT() asm volatile("cp.async.commit_group;" ::: "memory")
#define CP_WAIT1()  asm volatile("cp.async.wait_group 1;" ::: "memory")

static __device__ __forceinline__ int isqrt_le(int rem) {
    int t = (int)sqrtf((float)rem);
    while (t * t > rem) --t;
    while ((t + 1) * (t + 1) <= rem) ++t;
    return t;
}
static __device__ __forceinline__ unsigned ofloat(float v) {
    unsigned u = __float_as_uint(v);
    return (u & 0x80000000u) ? ~u : (u | 0x80000000u);
}
static __device__ __forceinline__ float defloat(unsigned m) {
    unsigned u = (m & 0x80000000u) ? (m & 0x7FFFFFFFu) : ~m;
    return __uint_as_float(u);
}

// ---------------- K0: fused setup (fp16 convert + m2 + zero Y/cnt) ----------------
__global__ void k_setup(const float* __restrict__ x, const float* __restrict__ mw) {
    int r = blockIdx.x, tid = threadIdx.x;
    if (r < BSZ) {
        float4 v = ((const float4*)(x + (size_t)r * DDIM))[tid];
        __half* dh = g_xh + (size_t)r * DDIM;
        ((__half2*)dh)[tid * 2]     = __halves2half2(__float2half_rn(v.x), __float2half_rn(v.y));
        ((__half2*)dh)[tid * 2 + 1] = __halves2half2(__float2half_rn(v.z), __float2half_rn(v.w));
    } else {
        int m = r - BSZ;
        float4 v = ((const float4*)(mw + (size_t)m * DDIM))[tid];
        __half* dh = g_mh + (size_t)m * DDIM;
        ((__half2*)dh)[tid * 2]     = __halves2half2(__float2half_rn(v.x), __float2half_rn(v.y));
        ((__half2*)dh)[tid * 2 + 1] = __halves2half2(__float2half_rn(v.z), __float2half_rn(v.w));
        ((float4*)(g_Y + (size_t)m * DDIM))[tid] = make_float4(0.f, 0.f, 0.f, 0.f);
        if (tid == 0) g_cnt[m] = 0.f;
        float s = v.x * v.x + v.y * v.y + v.z * v.z + v.w * v.w;
        #pragma unroll
        for (int o = 16; o; o >>= 1) s += __shfl_down_sync(0xFFFFFFFFu, s, o);
        __shared__ float ws[8];
        if ((tid & 31) == 0) ws[tid >> 5] = s;
        __syncthreads();
        if (tid == 0) {
            float t = 0.f;
            #pragma unroll
            for (int i = 0; i < 8; i++) t += ws[i];
            g_m2[m] = t;
        }
    }
}

// ---------------- K1a: fp16 MMA screen -> per-tile row mins + candidate lists ----------------
#define K1_PITCH 72
#define K1_ASZH (128 * K1_PITCH)
#define K1_STAGEH (K1_ASZH + 256 * K1_PITCH)
#define K1_SMEM (3 * K1_STAGEH * 2 + 1024)
__global__ void __launch_bounds__(512, 1) k1a_score() {
    extern __shared__ __half sh[];
    float* m2s = (float*)(sh + 3 * K1_STAGEH);
    __shared__ unsigned rowmin[128];
    __shared__ int ccnt[128];
    uint32_t sbase = smem_u32(sh);

    int tid = threadIdx.x;
    int lane = tid & 31, wid = tid >> 5;
    int warpM = wid & 3, warpN = wid >> 2;
    int gid = lane >> 2, tig = lane & 3;
    int lrow = lane & 15, lsel = (lane >> 4) * 8;
    int n0 = blockIdx.x * 256, b0 = blockIdx.y * 128;

    if (tid < 256) m2s[tid] = g_m2[n0 + tid];
    if (tid < 128) { rowmin[tid] = 0xFFFFFFFFu; ccnt[tid] = 0; }

    float acc[2][8][4];
    #pragma unroll
    for (int a = 0; a < 2; a++)
        #pragma unroll
        for (int b = 0; b < 8; b++)
            #pragma unroll
            for (int c = 0; c < 4; c++) acc[a][b][c] = 0.f;

    auto load_tile = [&](int i) {
        int s = i % 3;
        int k0 = i * 64;
        uint32_t stage = sbase + 2u * (uint32_t)(s * K1_STAGEH);
        #pragma unroll
        for (int u = 0; u < 2; u++) {
            int ch = tid + u * 512;
            int row = ch >> 3, kc = (ch & 7) * 8;
            cp16(stage + 2u * (uint32_t)(row * K1_PITCH + kc),
                 g_xh + (size_t)(b0 + row) * DDIM + k0 + kc);
        }
        #pragma unroll
        for (int u = 0; u < 4; u++) {
            int ch = tid + u * 512;
            int row = ch >> 3, kc = (ch & 7) * 8;
            cp16(stage + 2u * (uint32_t)(K1_ASZH + row * K1_PITCH + kc),
                 g_mh + (size_t)(n0 + row) * DDIM + k0 + kc);
        }
    };

    load_tile(0); CP_COMMIT();
    load_tile(1); CP_COMMIT();

    for (int i = 0; i < 16; i++) {
        CP_WAIT1();
        __syncthreads();
        if (i + 2 < 16) load_tile(i + 2);
        CP_COMMIT();

        uint32_t stage = sbase + 2u * (uint32_t)((i % 3) * K1_STAGEH);
        #pragma unroll
        for (int ks = 0; ks < 4; ks++) {
            int kb = ks * 16;
            uint32_t ah[2][4];
            #pragma unroll
            for (int mt = 0; mt < 2; mt++)
                ldsm_x4(ah[mt], stage + 2u * (uint32_t)((warpM * 32 + mt * 16 + lrow) * K1_PITCH + kb + lsel));
            uint32_t bh[8][2];
            #pragma unroll
            for (int pr = 0; pr < 4; pr++) {
                uint32_t t[4];
                ldsm_x4(t, stage + 2u * (uint32_t)(K1_ASZH + (warpN * 64 + pr * 16 + lrow) * K1_PITCH + kb + lsel));
                bh[pr * 2][0] = t[0]; bh[pr * 2 + 1][0] = t[1];
                bh[pr * 2][1] = t[2]; bh[pr * 2 + 1][1] = t[3];
            }
            #pragma unroll
            for (int mt = 0; mt < 2; mt++)
                #pragma unroll
                for (int nt = 0; nt < 8; nt++)
                    mma_f16(acc[mt][nt], ah[mt], bh[nt]);
        }
    }
    __syncthreads();

    // epilogue pass 1: per-row tile-min
    #pragma unroll
    for (int mt = 0; mt < 2; mt++) {
        int rl = warpM * 32 + mt * 16 + gid;
        unsigned umin0 = 0xFFFFFFFFu, umin1 = 0xFFFFFFFFu;
        #pragma unroll
        for (int nt = 0; nt < 8; nt++) {
            int cl = warpN * 64 + nt * 8 + tig * 2;
            __half2 h0 = __floats2half2_rn(m2s[cl]     - 2.0f * acc[mt][nt][0],
                                           m2s[cl + 1] - 2.0f * acc[mt][nt][1]);
            __half2 h1 = __floats2half2_rn(m2s[cl]     - 2.0f * acc[mt][nt][2],
                                           m2s[cl + 1] - 2.0f * acc[mt][nt][3]);
            unsigned u;
            u = ofloat(__low2float(h0));  umin0 = u < umin0 ? u : umin0;
            u = ofloat(__high2float(h0)); umin0 = u < umin0 ? u : umin0;
            u = ofloat(__low2float(h1));  umin1 = u < umin1 ? u : umin1;
            u = ofloat(__high2float(h1)); umin1 = u < umin1 ? u : umin1;
        }
        atomicMin(&rowmin[rl], umin0);
        atomicMin(&rowmin[rl + 8], umin1);
    }
    __syncthreads();

    // epilogue pass 2: candidates within tilemin + MARGIN
    unsigned* candsm = (unsigned*)sh;
    #pragma unroll
    for (int mt = 0; mt < 2; mt++) {
        int rl = warpM * 32 + mt * 16 + gid;
        float th0 = defloat(rowmin[rl]) + MARGIN;
        float th1 = defloat(rowmin[rl + 8]) + MARGIN;
        #pragma unroll
        for (int nt = 0; nt < 8; nt++) {
            int cl = warpN * 64 + nt * 8 + tig * 2;
            __half2 h0 = __floats2half2_rn(m2s[cl]     - 2.0f * acc[mt][nt][0],
                                           m2s[cl + 1] - 2.0f * acc[mt][nt][1]);
            __half2 h1 = __floats2half2_rn(m2s[cl]     - 2.0f * acc[mt][nt][2],
                                           m2s[cl + 1] - 2.0f * acc[mt][nt][3]);
            #pragma unroll
            for (int j = 0; j < 2; j++) {
                __half hv0 = j ? __high2half(h0) : __low2half(h0);
                __half hv1 = j ? __high2half(h1) : __low2half(h1);
                int n = n0 + cl + j;
                if (__half2float(hv0) <= th0) {
                    int pos = atomicAdd(&ccnt[rl], 1);
                    if (pos < CAP)
                        candsm[rl * CAP + pos] = ((unsigned)n << 16) | (unsigned)__half_as_ushort(hv0);
                }
                if (__half2float(hv1) <= th1) {
                    int pos = atomicAdd(&ccnt[rl + 8], 1);
                    if (pos < CAP)
                        candsm[(rl + 8) * CAP + pos] = ((unsigned)n << 16) | (unsigned)__half_as_ushort(hv1);
                }
            }
        }
    }
    __syncthreads();

    #pragma unroll
    for (int u = 0; u < 4; u++) {
        int idx = tid + u * 512;
        int row = idx >> 4, c = idx & 15;
        g_cand[((size_t)(b0 + row) * 16 + blockIdx.x) * CAP + c] = candsm[row * CAP + c];
    }
    if (tid < 128) {
        g_tmin[(size_t)(b0 + tid) * 16 + blockIdx.x] = rowmin[tid];
        g_ccnt[(size_t)(b0 + tid) * 16 + blockIdx.x] = ccnt[tid];
    }
}

// ---------------- K1b: candidate refine (warp-parallel) + fused scatter ----------------
__global__ void __launch_bounds__(256) k1b_refine(const float* __restrict__ x,
                                                  const float* __restrict__ mw) {
    __shared__ float xs[DDIM];
    __shared__ unsigned tm[16];
    __shared__ int cnts[16];
    __shared__ int cand[512];
    __shared__ int ncand;
    __shared__ float thr;
    __shared__ unsigned long long bkey;

    int b = blockIdx.x, tid = threadIdx.x;
    int lane = tid & 31, wid = tid >> 5;

    if (tid < 16) { tm[tid] = g_tmin[(size_t)b * 16 + tid]; cnts[tid] = g_ccnt[(size_t)b * 16 + tid]; }
    if (tid == 0) { ncand = 0; bkey = 0xFFFFFFFFFFFFFFFFull; }
    #pragma unroll
    for (int q = 0; q < 4; q++) xs[tid + q * 256] = x[(size_t)b * DDIM + tid + q * 256];
    __syncthreads();
    if (tid == 0) {
        unsigned m = tm[0];
        #pragma unroll
        for (int i = 1; i < 16; i++) m = tm[i] < m ? tm[i] : m;
        thr = defloat(m) + MARGIN;
    }
    __syncthreads();

    float th = thr;
    #pragma unroll
    for (int t = 0; t < 16; t++) {
        if (defloat(tm[t]) > th) continue;
        int ct = cnts[t];
        if (ct <= CAP) {
            if (tid < ct) {
                unsigned w = g_cand[((size_t)b * 16 + t) * CAP + tid];
                float sc = __half2float(__ushort_as_half((unsigned short)(w & 0xFFFFu)));
                if (sc <= th) {
                    int pos = atomicAdd(&ncand, 1);
                    if (pos < 512) cand[pos] = (int)(w >> 16);
                }
            }
        } else {
            if (tid < 256) {
                int pos = atomicAdd(&ncand, 1);
                if (pos < 512) cand[pos] = t * 256 + tid;
            }
        }
    }
    __syncthreads();

    // warp-parallel exact fp32 refine: warp w handles candidates w, w+8, ...
    int nc = min(ncand, 512);
    for (int c = wid; c < nc; c += 8) {
        int n = cand[c];
        const float* mr = mw + (size_t)n * DDIM;
        float p = 0.f;
        #pragma unroll
        for (int q = 0; q < 32; q++) p += xs[lane + q * 32] * mr[lane + q * 32];
        #pragma unroll
        for (int o = 16; o; o >>= 1) p += __shfl_down_sync(0xFFFFFFFFu, p, o);
        if (lane == 0) {
            float sc = g_m2[n] - 2.0f * p;
            unsigned long long k = ((unsigned long long)ofloat(sc) << 32) | (unsigned)n;
            atomicMin(&bkey, k);
        }
    }
    __syncthreads();

    // fused scatter: accumulate this x row into its BMU cell
    int p = (int)(bkey & 0xFFFFFFFFull);
    if (tid == 0) {
        g_bmu[b] = bkey;
        atomicAdd(&g_cnt[p], 1.0f);
    }
    float* yr = g_Y + (size_t)p * DDIM;
    #pragma unroll
    for (int q = 0; q < 4; q++)
        atomicAdd(&yr[tid + q * 256], xs[tid + q * 256]);
}

// ---------------- K3a: T2[pi,nj] = sum_pj e[|pj-nj|] * cnt[pi,pj] ----------------
__global__ __launch_bounds__(256) void k_T2() {
    __shared__ float cnts[NODES];
    __shared__ float e[64];
    int tid = threadIdx.x;
    float c2 = neg_inv_2r2();
    if (tid < 64) e[tid] = expf((float)(tid * tid) * c2);
    for (int i = tid; i < NODES; i += 256) cnts[i] = g_cnt[i];
    __syncthreads();
    int idx = blockIdx.x * 256 + tid;
    int pi = idx >> 6, nj = idx & 63;
    float s = 0.f;
    #pragma unroll 8
    for (int pj = 0; pj < 64; pj++) s += e[abs(pj - nj)] * cnts[pi * 64 + pj];
    g_T2[idx] = s;
}

// ---------------- K3b: cs[n] = sum_pi ei*T2[pi,nj] - corner corrections ----------------
__global__ __launch_bounds__(256) void k_colsum() {
    __shared__ float cnts[NODES];
    __shared__ float T2s[NODES];
    __shared__ float e[64];
    int tid = threadIdx.x;
    int ni = blockIdx.x;
    float c2 = neg_inv_2r2();
    if (tid < 64) e[tid] = expf((float)(tid * tid) * c2);
    for (int i = tid; i < NODES; i += 256) { cnts[i] = g_cnt[i]; T2s[i] = g_T2[i]; }
    __syncthreads();
    int nj = tid >> 2, part = tid & 3;
    float s = 0.f;
    for (int pi = part; pi < GRIDW; pi += 4) {
        int di = pi - ni;
        float ei = e[abs(di)];
        s += ei * T2s[pi * 64 + nj];
        int t = isqrt_le(D2_MAX - di * di);
        for (int pj = 0; pj <= nj - t - 1; pj++) s -= ei * e[nj - pj] * cnts[pi * 64 + pj];
        for (int pj = nj + t + 1; pj < GRIDW; pj++) s -= ei * e[pj - nj] * cnts[pi * 64 + pj];
    }
    s += __shfl_down_sync(0xFFFFFFFFu, s, 2);
    s += __shfl_down_sync(0xFFFFFFFFu, s, 1);
    if (part == 0) g_cs[ni * 64 + nj] = s;
}

// ---------------- K4a: conv over pj (pj-outer, 8 accumulators) ----------------
__global__ __launch_bounds__(256) void k_convA() {
    __shared__ float Ys[64][128];
    __shared__ float e[64];
    int tid = threadIdx.x;
    int pi = blockIdx.y;
    int d0 = blockIdx.x * 128;
    float c2 = neg_inv_2r2();
    if (tid < 64) e[tid] = expf((float)(tid * tid) * c2);
    for (int i = tid; i < 2048; i += 256) {
        int row = i >> 5, c4 = (i & 31) * 4;
        *(float4*)&Ys[row][c4] = *(const float4*)(g_Y + ((size_t)pi * 64 + row) * DDIM + d0 + c4);
    }
    __syncthreads();
    int d4 = (tid & 31) * 4;
    int njb = tid >> 5;
    float4 a8[8];
    #pragma unroll
    for (int g = 0; g < 8; g++) a8[g] = make_float4(0.f, 0.f, 0.f, 0.f);
    for (int pj = 0; pj < 64; pj++) {
        float4 y = *(const float4*)&Ys[pj][d4];
        #pragma unroll
        for (int g = 0; g < 8; g++) {
            float w = e[abs(pj - (njb * 8 + g))];
            a8[g].x += w * y.x; a8[g].y += w * y.y; a8[g].z += w * y.z; a8[g].w += w * y.w;
        }
    }
    #pragma unroll
    for (int g = 0; g < 8; g++)
        *(float4*)(g_T + ((size_t)pi * 64 + njb * 8 + g) * DDIM + d0 + d4) = a8[g];
}

// ---------------- K4b: conv over pi + fused update (pi-outer) ----------------
__global__ __launch_bounds__(256) void k_convB(const float* __restrict__ mw,
                                               float* __restrict__ out) {
    __shared__ float Ts[64][128];
    __shared__ float e[64];
    __shared__ float css[64];
    int tid = threadIdx.x;
    int nj = blockIdx.y;
    int d0 = blockIdx.x * 128;
    float c2 = neg_inv_2r2();
    if (tid < 64) { e[tid] = expf((float)(tid * tid) * c2); css[tid] = g_cs[tid * 64 + nj]; }
    for (int i = tid; i < 2048; i += 256) {
        int row = i >> 5, c4 = (i & 31) * 4;
        *(float4*)&Ts[row][c4] = *(const float4*)(g_T + ((size_t)row * 64 + nj) * DDIM + d0 + c4);
    }
    __syncthreads();
    const float scale = 0.5f / 8192.0f;
    int d4 = (tid & 31) * 4;
    int nib = tid >> 5;
    float4 a8[8];
    #pragma unroll
    for (int g = 0; g < 8; g++) a8[g] = make_float4(0.f, 0.f, 0.f, 0.f);
    for (int pi = 0; pi < 64; pi++) {
        float4 t = *(const float4*)&Ts[pi][d4];
        #pragma unroll
        for (int g = 0; g < 8; g++) {
            float w = e[abs(pi - (nib * 8 + g))];
            a8[g].x += w * t.x; a8[g].y += w * t.y; a8[g].z += w * t.z; a8[g].w += w * t.w;
        }
    }
    #pragma unroll
    for (int g = 0; g < 8; g++) {
        int ni = nib * 8 + g;
        float cs = css[ni];
        size_t off = ((size_t)ni * 64 + nj) * DDIM + d0 + d4;
        float4 m = *(const float4*)(mw + off);
        float4 o;
        o.x = m.x + scale * (a8[g].x - cs * m.x);
        o.y = m.y + scale * (a8[g].y - cs * m.y);
        o.z = m.z + scale * (a8[g].z - cs * m.z);
        o.w = m.w + scale * (a8[g].w - cs * m.w);
        *(float4*)(out + off) = o;
    }
}

// ---------------- K4c: out-of-radius correction (corner nodes only) ----------------
__global__ __launch_bounds__(256) void k_corr(float* __restrict__ out) {
    int n = blockIdx.x;
    int ni = n >> 6, nj = n & 63;
    int u = max(ni, 63 - ni), v = max(nj, 63 - nj);
    if (u * u + v * v <= D2_MAX) return;
    __shared__ float e[64];
    int tid = threadIdx.x;
    float c2 = neg_inv_2r2();
    if (tid < 64) e[tid] = expf((float)(tid * tid) * c2);
    __syncthreads();
    int d4 = tid * 4;
    float4 acc = make_float4(0.f, 0.f, 0.f, 0.f);
    for (int pi = 0; pi < GRIDW; pi++) {
        int di = pi - ni;
        int t = isqrt_le(D2_MAX - di * di);
        float ei = e[abs(di)];
        for (int pj = 0; pj <= nj - t - 1; pj++) {
            float w = ei * e[nj - pj];
            float4 y = *(const float4*)(g_Y + ((size_t)pi * 64 + pj) * DDIM + d4);
            acc.x += w * y.x; acc.y += w * y.y; acc.z += w * y.z; acc.w += w * y.w;
        }
        for (int pj = nj + t + 1; pj < GRIDW; pj++) {
            float w = ei * e[pj - nj];
            float4 y = *(const float4*)(g_Y + ((size_t)pi * 64 + pj) * DDIM + d4);
            acc.x += w * y.x; acc.y += w * y.y; acc.z += w * y.z; acc.w += w * y.w;
        }
    }
    const float scale = 0.5f / 8192.0f;
    size_t off = (size_t)n * DDIM + d4;
    float4 o = *(float4*)(out + off);
    o.x -= scale * acc.x; o.y -= scale * acc.y; o.z -= scale * acc.z; o.w -= scale * acc.w;
    *(float4*)(out + off) = o;
}

// ---------------- launch ----------------
extern "C" void kernel_launch(void* const* d_in, const int* in_sizes, int n_in,
                              void* d_out, int out_size) {
    const float* x  = (const float*)d_in[0];
    const float* mw = (const float*)d_in[1];
    float* out = (float*)d_out;

    cudaFuncSetAttribute(k1a_score, cudaFuncAttributeMaxDynamicSharedMemorySize, K1_SMEM);

    k_setup<<<BSZ + NODES, 256>>>(x, mw);
    dim3 g1(NODES / 256, BSZ / 128);             // 16 x 64
    k1a_score<<<g1, 512, K1_SMEM>>>();
    k1b_refine<<<BSZ, 256>>>(x, mw);
    k_T2<<<NODES / 256, 256>>>();
    k_colsum<<<GRIDW, 256>>>();
    dim3 gc(DDIM / 128, GRIDW);
    k_convA<<<gc, 256>>>();
    k_convB<<<gc, 256>>>(mw, out);
    k_corr<<<NODES, 256>>>(out);
}

// round 15
// speedup vs baseline: 1.0609x; 1.0609x over previous
#include <cuda_runtime.h>
#include <cuda_fp16.h>
#include <cstdint>

#define BSZ   8192
#define DDIM  1024
#define NODES 4096
#define GRIDW 64
#define D2_MAX 4956          // integer d2 <= 4956 <=> sqrt(d2) <= radius (exact)
#define MARGIN 0.6f
#define CAP 16

// ---------------- scratch ----------------
__device__ unsigned long long g_bmu[BSZ];
__device__ unsigned g_tmin[BSZ * 16];          // per-row per-tile min (ordered u32)
__device__ int g_ccnt[BSZ * 16];               // per-row per-tile candidate count
__device__ unsigned g_cand[(size_t)BSZ * 16 * CAP];  // (node<<16)|fp16 score
__device__ float g_Y[NODES * DDIM];
__device__ float g_T[NODES * DDIM];
__device__ float g_cnt[NODES];
__device__ float g_m2[NODES];
__device__ float g_cs[NODES];
__device__ __half g_xh[BSZ * DDIM];
__device__ __half g_mh[NODES * DDIM];

__device__ __forceinline__ float neg_inv_2r2() {
    const float r = 70.4f + 1e-6f;
    return -1.0f / (2.0f * r * r);
}
static __device__ __forceinline__ uint32_t smem_u32(const void* p) {
    uint32_t a;
    asm("{ .reg .u64 t; cvta.to.shared.u64 t, %1; cvt.u32.u64 %0, t; }" : "=r"(a) : "l"(p));
    return a;
}
static __device__ __forceinline__ void mma_f16(float* c, const uint32_t* a, const uint32_t* b) {
    asm volatile(
        "mma.sync.aligned.m16n8k16.row.col.f32.f16.f16.f32 "
        "{%0,%1,%2,%3}, {%4,%5,%6,%7}, {%8,%9}, {%0,%1,%2,%3};"
        : "+f"(c[0]), "+f"(c[1]), "+f"(c[2]), "+f"(c[3])
        : "r"(a[0]), "r"(a[1]), "r"(a[2]), "r"(a[3]), "r"(b[0]), "r"(b[1]));
}
static __device__ __forceinline__ void ldsm_x4(uint32_t* r, uint32_t addr) {
    asm volatile("ldmatrix.sync.aligned.m8n8.x4.shared.b16 {%0,%1,%2,%3}, [%4];"
                 : "=r"(r[0]), "=r"(r[1]), "=r"(r[2]), "=r"(r[3]) : "r"(addr));
}
static __device__ __forceinline__ void cp16(uint32_t dst, const void* src) {
    asm volatile("cp.async.cg.shared.global [%0], [%1], 16;" :: "r"(dst), "l"(src));
}
#define CP_COMMIT() asm volatile("cp.async.commit_group;" ::: "memory")
#define CP_WAIT1()  asm volatile("cp.async.wait_group 1;" ::: "memory")

static __device__ __forceinline__ int isqrt_le(int rem) {
    int t = (int)sqrtf((float)rem);
    while (t * t > rem) --t;
    while ((t + 1) * (t + 1) <= rem) ++t;
    return t;
}
static __device__ __forceinline__ unsigned ofloat(float v) {
    unsigned u = __float_as_uint(v);
    return (u & 0x80000000u) ? ~u : (u | 0x80000000u);
}
static __device__ __forceinline__ float defloat(unsigned m) {
    unsigned u = (m & 0x80000000u) ? (m & 0x7FFFFFFFu) : ~m;
    return __uint_as_float(u);
}

// ---------------- K0: fused setup (fp16 convert + m2 + zero Y/cnt) ----------------
__global__ void k_setup(const float* __restrict__ x, const float* __restrict__ mw) {
    int r = blockIdx.x, tid = threadIdx.x;
    if (r < BSZ) {
        float4 v = ((const float4*)(x + (size_t)r * DDIM))[tid];
        __half* dh = g_xh + (size_t)r * DDIM;
        ((__half2*)dh)[tid * 2]     = __halves2half2(__float2half_rn(v.x), __float2half_rn(v.y));
        ((__half2*)dh)[tid * 2 + 1] = __halves2half2(__float2half_rn(v.z), __float2half_rn(v.w));
    } else {
        int m = r - BSZ;
        float4 v = ((const float4*)(mw + (size_t)m * DDIM))[tid];
        __half* dh = g_mh + (size_t)m * DDIM;
        ((__half2*)dh)[tid * 2]     = __halves2half2(__float2half_rn(v.x), __float2half_rn(v.y));
        ((__half2*)dh)[tid * 2 + 1] = __halves2half2(__float2half_rn(v.z), __float2half_rn(v.w));
        ((float4*)(g_Y + (size_t)m * DDIM))[tid] = make_float4(0.f, 0.f, 0.f, 0.f);
        if (tid == 0) g_cnt[m] = 0.f;
        float s = v.x * v.x + v.y * v.y + v.z * v.z + v.w * v.w;
        #pragma unroll
        for (int o = 16; o; o >>= 1) s += __shfl_down_sync(0xFFFFFFFFu, s, o);
        __shared__ float ws[8];
        if ((tid & 31) == 0) ws[tid >> 5] = s;
        __syncthreads();
        if (tid == 0) {
            float t = 0.f;
            #pragma unroll
            for (int i = 0; i < 8; i++) t += ws[i];
            g_m2[m] = t;
        }
    }
}

// ---------------- K1a: fp16 MMA screen -> per-tile row mins + candidate lists ----------------
#define K1_PITCH 72
#define K1_ASZH (128 * K1_PITCH)
#define K1_STAGEH (K1_ASZH + 256 * K1_PITCH)
#define K1_SMEM (3 * K1_STAGEH * 2 + 1024)
__global__ void __launch_bounds__(512, 1) k1a_score() {
    extern __shared__ __half sh[];
    float* m2s = (float*)(sh + 3 * K1_STAGEH);
    __shared__ unsigned rowmin[128];
    __shared__ int ccnt[128];
    uint32_t sbase = smem_u32(sh);

    int tid = threadIdx.x;
    int lane = tid & 31, wid = tid >> 5;
    int warpM = wid & 3, warpN = wid >> 2;
    int gid = lane >> 2, tig = lane & 3;
    int lrow = lane & 15, lsel = (lane >> 4) * 8;
    int n0 = blockIdx.x * 256, b0 = blockIdx.y * 128;

    if (tid < 256) m2s[tid] = g_m2[n0 + tid];
    if (tid < 128) { rowmin[tid] = 0xFFFFFFFFu; ccnt[tid] = 0; }

    float acc[2][8][4];
    #pragma unroll
    for (int a = 0; a < 2; a++)
        #pragma unroll
        for (int b = 0; b < 8; b++)
            #pragma unroll
            for (int c = 0; c < 4; c++) acc[a][b][c] = 0.f;

    auto load_tile = [&](int i) {
        int s = i % 3;
        int k0 = i * 64;
        uint32_t stage = sbase + 2u * (uint32_t)(s * K1_STAGEH);
        #pragma unroll
        for (int u = 0; u < 2; u++) {
            int ch = tid + u * 512;
            int row = ch >> 3, kc = (ch & 7) * 8;
            cp16(stage + 2u * (uint32_t)(row * K1_PITCH + kc),
                 g_xh + (size_t)(b0 + row) * DDIM + k0 + kc);
        }
        #pragma unroll
        for (int u = 0; u < 4; u++) {
            int ch = tid + u * 512;
            int row = ch >> 3, kc = (ch & 7) * 8;
            cp16(stage + 2u * (uint32_t)(K1_ASZH + row * K1_PITCH + kc),
                 g_mh + (size_t)(n0 + row) * DDIM + k0 + kc);
        }
    };

    load_tile(0); CP_COMMIT();
    load_tile(1); CP_COMMIT();

    for (int i = 0; i < 16; i++) {
        CP_WAIT1();
        __syncthreads();
        if (i + 2 < 16) load_tile(i + 2);
        CP_COMMIT();

        uint32_t stage = sbase + 2u * (uint32_t)((i % 3) * K1_STAGEH);
        #pragma unroll
        for (int ks = 0; ks < 4; ks++) {
            int kb = ks * 16;
            uint32_t ah[2][4];
            #pragma unroll
            for (int mt = 0; mt < 2; mt++)
                ldsm_x4(ah[mt], stage + 2u * (uint32_t)((warpM * 32 + mt * 16 + lrow) * K1_PITCH + kb + lsel));
            uint32_t bh[8][2];
            #pragma unroll
            for (int pr = 0; pr < 4; pr++) {
                uint32_t t[4];
                ldsm_x4(t, stage + 2u * (uint32_t)(K1_ASZH + (warpN * 64 + pr * 16 + lrow) * K1_PITCH + kb + lsel));
                bh[pr * 2][0] = t[0]; bh[pr * 2 + 1][0] = t[1];
                bh[pr * 2][1] = t[2]; bh[pr * 2 + 1][1] = t[3];
            }
            #pragma unroll
            for (int mt = 0; mt < 2; mt++)
                #pragma unroll
                for (int nt = 0; nt < 8; nt++)
                    mma_f16(acc[mt][nt], ah[mt], bh[nt]);
        }
    }
    __syncthreads();

    // epilogue pass 1: per-row tile-min
    #pragma unroll
    for (int mt = 0; mt < 2; mt++) {
        int rl = warpM * 32 + mt * 16 + gid;
        unsigned umin0 = 0xFFFFFFFFu, umin1 = 0xFFFFFFFFu;
        #pragma unroll
        for (int nt = 0; nt < 8; nt++) {
            int cl = warpN * 64 + nt * 8 + tig * 2;
            __half2 h0 = __floats2half2_rn(m2s[cl]     - 2.0f * acc[mt][nt][0],
                                           m2s[cl + 1] - 2.0f * acc[mt][nt][1]);
            __half2 h1 = __floats2half2_rn(m2s[cl]     - 2.0f * acc[mt][nt][2],
                                           m2s[cl + 1] - 2.0f * acc[mt][nt][3]);
            unsigned u;
            u = ofloat(__low2float(h0));  umin0 = u < umin0 ? u : umin0;
            u = ofloat(__high2float(h0)); umin0 = u < umin0 ? u : umin0;
            u = ofloat(__low2float(h1));  umin1 = u < umin1 ? u : umin1;
            u = ofloat(__high2float(h1)); umin1 = u < umin1 ? u : umin1;
        }
        atomicMin(&rowmin[rl], umin0);
        atomicMin(&rowmin[rl + 8], umin1);
    }
    __syncthreads();

    // epilogue pass 2: candidates within tilemin + MARGIN
    unsigned* candsm = (unsigned*)sh;
    #pragma unroll
    for (int mt = 0; mt < 2; mt++) {
        int rl = warpM * 32 + mt * 16 + gid;
        float th0 = defloat(rowmin[rl]) + MARGIN;
        float th1 = defloat(rowmin[rl + 8]) + MARGIN;
        #pragma unroll
        for (int nt = 0; nt < 8; nt++) {
            int cl = warpN * 64 + nt * 8 + tig * 2;
            __half2 h0 = __floats2half2_rn(m2s[cl]     - 2.0f * acc[mt][nt][0],
                                           m2s[cl + 1] - 2.0f * acc[mt][nt][1]);
            __half2 h1 = __floats2half2_rn(m2s[cl]     - 2.0f * acc[mt][nt][2],
                                           m2s[cl + 1] - 2.0f * acc[mt][nt][3]);
            #pragma unroll
            for (int j = 0; j < 2; j++) {
                __half hv0 = j ? __high2half(h0) : __low2half(h0);
                __half hv1 = j ? __high2half(h1) : __low2half(h1);
                int n = n0 + cl + j;
                if (__half2float(hv0) <= th0) {
                    int pos = atomicAdd(&ccnt[rl], 1);
                    if (pos < CAP)
                        candsm[rl * CAP + pos] = ((unsigned)n << 16) | (unsigned)__half_as_ushort(hv0);
                }
                if (__half2float(hv1) <= th1) {
                    int pos = atomicAdd(&ccnt[rl + 8], 1);
                    if (pos < CAP)
                        candsm[(rl + 8) * CAP + pos] = ((unsigned)n << 16) | (unsigned)__half_as_ushort(hv1);
                }
            }
        }
    }
    __syncthreads();

    #pragma unroll
    for (int u = 0; u < 4; u++) {
        int idx = tid + u * 512;
        int row = idx >> 4, c = idx & 15;
        g_cand[((size_t)(b0 + row) * 16 + blockIdx.x) * CAP + c] = candsm[row * CAP + c];
    }
    if (tid < 128) {
        g_tmin[(size_t)(b0 + tid) * 16 + blockIdx.x] = rowmin[tid];
        g_ccnt[(size_t)(b0 + tid) * 16 + blockIdx.x] = ccnt[tid];
    }
}

// ---------------- K1b: candidate refine + fused scatter (R13 serial version) ----------------
__global__ void __launch_bounds__(256) k1b_refine(const float* __restrict__ x,
                                                  const float* __restrict__ mw) {
    __shared__ float xs[DDIM];
    __shared__ unsigned tm[16];
    __shared__ int cnts[16];
    __shared__ float red[8];
    __shared__ int cand[512];
    __shared__ int ncand;
    __shared__ float thr;
    __shared__ unsigned long long bkey;

    int b = blockIdx.x, tid = threadIdx.x;
    int lane = tid & 31, wid = tid >> 5;

    if (tid < 16) { tm[tid] = g_tmin[(size_t)b * 16 + tid]; cnts[tid] = g_ccnt[(size_t)b * 16 + tid]; }
    if (tid == 0) { ncand = 0; bkey = 0xFFFFFFFFFFFFFFFFull; }
    #pragma unroll
    for (int q = 0; q < 4; q++) xs[tid + q * 256] = x[(size_t)b * DDIM + tid + q * 256];
    __syncthreads();
    if (tid == 0) {
        unsigned m = tm[0];
        #pragma unroll
        for (int i = 1; i < 16; i++) m = tm[i] < m ? tm[i] : m;
        thr = defloat(m) + MARGIN;
    }
    __syncthreads();

    float th = thr;
    #pragma unroll
    for (int t = 0; t < 16; t++) {
        if (defloat(tm[t]) > th) continue;
        int ct = cnts[t];
        if (ct <= CAP) {
            if (tid < ct) {
                unsigned w = g_cand[((size_t)b * 16 + t) * CAP + tid];
                float sc = __half2float(__ushort_as_half((unsigned short)(w & 0xFFFFu)));
                if (sc <= th) {
                    int pos = atomicAdd(&ncand, 1);
                    if (pos < 512) cand[pos] = (int)(w >> 16);
                }
            }
        } else {
            if (tid < 256) {
                int pos = atomicAdd(&ncand, 1);
                if (pos < 512) cand[pos] = t * 256 + tid;
            }
        }
    }
    __syncthreads();

    int nc = min(ncand, 512);
    for (int c = 0; c < nc; c++) {
        int n = cand[c];
        const float* mr = mw + (size_t)n * DDIM;
        float p = 0.f;
        #pragma unroll
        for (int q = 0; q < 4; q++) p += xs[tid + q * 256] * mr[tid + q * 256];
        #pragma unroll
        for (int o = 16; o; o >>= 1) p += __shfl_down_sync(0xFFFFFFFFu, p, o);
        if (lane == 0) red[wid] = p;
        __syncthreads();
        if (tid == 0) {
            float dot = 0.f;
            #pragma unroll
            for (int i = 0; i < 8; i++) dot += red[i];
            float sc = g_m2[n] - 2.0f * dot;
            unsigned long long k = ((unsigned long long)ofloat(sc) << 32) | (unsigned)n;
            if (k < bkey) bkey = k;
        }
        __syncthreads();
    }

    // fused scatter: accumulate this x row into its BMU cell
    int p = (int)(bkey & 0xFFFFFFFFull);
    if (tid == 0) {
        g_bmu[b] = bkey;
        atomicAdd(&g_cnt[p], 1.0f);
    }
    float* yr = g_Y + (size_t)p * DDIM;
    #pragma unroll
    for (int q = 0; q < 4; q++)
        atomicAdd(&yr[tid + q * 256], xs[tid + q * 256]);
}

// ---------------- K3: cs[n] separable + corner correction (512 thr, isqrt table) ----------------
__global__ __launch_bounds__(512) void k_colsum() {
    __shared__ float cnts[NODES];
    __shared__ float e[64];
    __shared__ int tt[64];
    __shared__ float T2[64][65];
    int tid = threadIdx.x;
    int ni = blockIdx.x;
    float c2 = neg_inv_2r2();
    if (tid < 64) {
        e[tid] = expf((float)(tid * tid) * c2);
        tt[tid] = isqrt_le(D2_MAX - tid * tid);
    }
    for (int i = tid; i < NODES; i += 512) cnts[i] = g_cnt[i];
    __syncthreads();
    for (int idx = tid; idx < 4096; idx += 512) {
        int pi = idx >> 6, nj = idx & 63;
        float s = 0.f;
        #pragma unroll 8
        for (int pj = 0; pj < 64; pj++) s += e[abs(pj - nj)] * cnts[pi * 64 + pj];
        T2[pi][nj] = s;
    }
    __syncthreads();
    int nj = tid >> 3, part = tid & 7;
    float s = 0.f;
    for (int pi = part; pi < GRIDW; pi += 8) {
        int di = pi - ni;
        int adi = abs(di);
        float ei = e[adi];
        s += ei * T2[pi][nj];
        int t = tt[adi];
        for (int pj = 0; pj <= nj - t - 1; pj++) s -= ei * e[nj - pj] * cnts[pi * 64 + pj];
        for (int pj = nj + t + 1; pj < GRIDW; pj++) s -= ei * e[pj - nj] * cnts[pi * 64 + pj];
    }
    s += __shfl_down_sync(0xFFFFFFFFu, s, 4);
    s += __shfl_down_sync(0xFFFFFFFFu, s, 2);
    s += __shfl_down_sync(0xFFFFFFFFu, s, 1);
    if (part == 0) g_cs[ni * 64 + nj] = s;
}

// ---------------- K4a: conv over pj (pj-outer, 8 accumulators) ----------------
__global__ __launch_bounds__(256) void k_convA() {
    __shared__ float Ys[64][128];
    __shared__ float e[64];
    int tid = threadIdx.x;
    int pi = blockIdx.y;
    int d0 = blockIdx.x * 128;
    float c2 = neg_inv_2r2();
    if (tid < 64) e[tid] = expf((float)(tid * tid) * c2);
    for (int i = tid; i < 2048; i += 256) {
        int row = i >> 5, c4 = (i & 31) * 4;
        *(float4*)&Ys[row][c4] = *(const float4*)(g_Y + ((size_t)pi * 64 + row) * DDIM + d0 + c4);
    }
    __syncthreads();
    int d4 = (tid & 31) * 4;
    int njb = tid >> 5;
    float4 a8[8];
    #pragma unroll
    for (int g = 0; g < 8; g++) a8[g] = make_float4(0.f, 0.f, 0.f, 0.f);
    for (int pj = 0; pj < 64; pj++) {
        float4 y = *(const float4*)&Ys[pj][d4];
        #pragma unroll
        for (int g = 0; g < 8; g++) {
            float w = e[abs(pj - (njb * 8 + g))];
            a8[g].x += w * y.x; a8[g].y += w * y.y; a8[g].z += w * y.z; a8[g].w += w * y.w;
        }
    }
    #pragma unroll
    for (int g = 0; g < 8; g++)
        *(float4*)(g_T + ((size_t)pi * 64 + njb * 8 + g) * DDIM + d0 + d4) = a8[g];
}

// ---------------- K4b: conv over pi + fused update (pi-outer) ----------------
__global__ __launch_bounds__(256) void k_convB(const float* __restrict__ mw,
                                               float* __restrict__ out) {
    __shared__ float Ts[64][128];
    __shared__ float e[64];
    __shared__ float css[64];
    int tid = threadIdx.x;
    int nj = blockIdx.y;
    int d0 = blockIdx.x * 128;
    float c2 = neg_inv_2r2();
    if (tid < 64) { e[tid] = expf((float)(tid * tid) * c2); css[tid] = g_cs[tid * 64 + nj]; }
    for (int i = tid; i < 2048; i += 256) {
        int row = i >> 5, c4 = (i & 31) * 4;
        *(float4*)&Ts[row][c4] = *(const float4*)(g_T + ((size_t)row * 64 + nj) * DDIM + d0 + c4);
    }
    __syncthreads();
    const float scale = 0.5f / 8192.0f;
    int d4 = (tid & 31) * 4;
    int nib = tid >> 5;
    float4 a8[8];
    #pragma unroll
    for (int g = 0; g < 8; g++) a8[g] = make_float4(0.f, 0.f, 0.f, 0.f);
    for (int pi = 0; pi < 64; pi++) {
        float4 t = *(const float4*)&Ts[pi][d4];
        #pragma unroll
        for (int g = 0; g < 8; g++) {
            float w = e[abs(pi - (nib * 8 + g))];
            a8[g].x += w * t.x; a8[g].y += w * t.y; a8[g].z += w * t.z; a8[g].w += w * t.w;
        }
    }
    #pragma unroll
    for (int g = 0; g < 8; g++) {
        int ni = nib * 8 + g;
        float cs = css[ni];
        size_t off = ((size_t)ni * 64 + nj) * DDIM + d0 + d4;
        float4 m = *(const float4*)(mw + off);
        float4 o;
        o.x = m.x + scale * (a8[g].x - cs * m.x);
        o.y = m.y + scale * (a8[g].y - cs * m.y);
        o.z = m.z + scale * (a8[g].z - cs * m.z);
        o.w = m.w + scale * (a8[g].w - cs * m.w);
        *(float4*)(out + off) = o;
    }
}

// ---------------- K4c: out-of-radius correction (corner nodes only) ----------------
__global__ __launch_bounds__(256) void k_corr(float* __restrict__ out) {
    int n = blockIdx.x;
    int ni = n >> 6, nj = n & 63;
    int u = max(ni, 63 - ni), v = max(nj, 63 - nj);
    if (u * u + v * v <= D2_MAX) return;
    __shared__ float e[64];
    int tid = threadIdx.x;
    float c2 = neg_inv_2r2();
    if (tid < 64) e[tid] = expf((float)(tid * tid) * c2);
    __syncthreads();
    int d4 = tid * 4;
    float4 acc = make_float4(0.f, 0.f, 0.f, 0.f);
    for (int pi = 0; pi < GRIDW; pi++) {
        int di = pi - ni;
        int t = isqrt_le(D2_MAX - di * di);
        float ei = e[abs(di)];
        for (int pj = 0; pj <= nj - t - 1; pj++) {
            float w = ei * e[nj - pj];
            float4 y = *(const float4*)(g_Y + ((size_t)pi * 64 + pj) * DDIM + d4);
            acc.x += w * y.x; acc.y += w * y.y; acc.z += w * y.z; acc.w += w * y.w;
        }
        for (int pj = nj + t + 1; pj < GRIDW; pj++) {
            float w = ei * e[pj - nj];
            float4 y = *(const float4*)(g_Y + ((size_t)pi * 64 + pj) * DDIM + d4);
            acc.x += w * y.x; acc.y += w * y.y; acc.z += w * y.z; acc.w += w * y.w;
        }
    }
    const float scale = 0.5f / 8192.0f;
    size_t off = (size_t)n * DDIM + d4;
    float4 o = *(float4*)(out + off);
    o.x -= scale * acc.x; o.y -= scale * acc.y; o.z -= scale * acc.z; o.w -= scale * acc.w;
    *(float4*)(out + off) = o;
}

// ---------------- launch ----------------
extern "C" void kernel_launch(void* const* d_in, const int* in_sizes, int n_in,
                              void* d_out, int out_size) {
    const float* x  = (const float*)d_in[0];
    const float* mw = (const float*)d_in[1];
    float* out = (float*)d_out;

    cudaFuncSetAttribute(k1a_score, cudaFuncAttributeMaxDynamicSharedMemorySize, K1_SMEM);

    k_setup<<<BSZ + NODES, 256>>>(x, mw);
    dim3 g1(NODES / 256, BSZ / 128);             // 16 x 64
    k1a_score<<<g1, 512, K1_SMEM>>>();
    k1b_refine<<<BSZ, 256>>>(x, mw);
    k_colsum<<<GRIDW, 512>>>();
    dim3 gc(DDIM / 128, GRIDW);
    k_convA<<<gc, 256>>>();
    k_convB<<<gc, 256>>>(mw, out);
    k_corr<<<NODES, 256>>>(out);
}